// round 4
// baseline (speedup 1.0000x reference)
#include <cuda_runtime.h>
#include <cuda_bf16.h>

// out[i, j] = J0(1000 * |p_i - s_j|) / (2*pi),  N=10000, M=5000 (fp32)
//
// MUFU/issue-bound kernel. Precision strategy:
//  - r = __fsqrt_rn(r2): matches JAX fp32 sqrt rounding so the large phase
//    argument xx = 1000*r - pi/4 tracks the reference's to < 1 ulp.
//  - Cody-Waite reduction mod 2pi (C1=6.28125: 9 mantissa bits, n*C1 exact
//    for n <= ~1000), then __sincosf on reduced arg in [-pi,pi] (err ~2^-21).
//  - single rsqrt.approx(ax) provides both amplitude and 1/ax (low-sensitivity
//    terms only): 4 MUFU per element total (RSQ, RSQ, SIN, COS).

#define KW        1000.0f
#define INV_2PI   0.15915494309189535f
// sqrt(0.636619772) * INV_2PI  (folds the 1/(2pi) output scale into amplitude)
#define SQRT_AMP_C 0.126977011f
#define MAGIC     12582912.0f      // 1.5 * 2^23
#define C1        6.28125f         // hi part of 2pi (exact in 9 bits)
#define C2        0.0019353071795864769f  // 2pi - C1

__device__ __forceinline__ float rsqrt_approx(float x) {
    float r; asm("rsqrt.approx.f32 %0, %1;" : "=f"(r) : "f"(x)); return r;
}

__device__ __noinline__ float j0_small_scaled(float ax) {
    // rare path (r < 0.008): exact reference rational polynomial
    float y = ax * ax;
    float num = 57568490574.0f + y * (-13362590354.0f + y * (651619640.7f
              + y * (-11214424.18f + y * (77392.33017f + y * (-184.9052456f)))));
    float den = 57568490411.0f + y * (1029532985.0f + y * (9494680.718f
              + y * (59272.64853f + y * (267.8532712f + y))));
    return __fdividef(num, den) * INV_2PI;
}

__device__ __forceinline__ float j0_scaled(float ax) {
    // returns J0(ax) * (1/2pi)
    if (__builtin_expect(ax < 8.0f, 0)) {
        return j0_small_scaled(ax);
    }
    float rsq = rsqrt_approx(ax);          // 1/sqrt(ax)
    float inv_ax = rsq * rsq;              // ~1/ax (low-sensitivity use only)
    float z  = 8.0f * inv_ax;
    float y2 = z * z;
    float xx = ax - 0.785398164f;
    // range-reduce xx mod 2pi (Cody-Waite)
    float t   = fmaf(xx, INV_2PI, MAGIC);
    float n   = t - MAGIC;
    float red = fmaf(n, -C1, xx);
    red       = fmaf(n, -C2, red);
    float s, c;
    __sincosf(red, &s, &c);
    float p0 = 1.0f + y2 * (-0.1098628627e-2f + y2 * (0.2734510407e-4f
             + y2 * (-0.2073370639e-5f + y2 * 0.2093887211e-6f)));
    float q0 = -0.1562499995e-1f + y2 * (0.1430488765e-3f + y2 * (-0.6911147651e-5f
             + y2 * (0.7621095161e-6f + y2 * (-0.934935152e-7f))));
    float amp = SQRT_AMP_C * rsq;          // sqrt(0.636619772/ax) / (2pi)
    return amp * (c * p0 - z * (s * q0));
}

__device__ __forceinline__ float4 row_vals(float px, float py,
                                           float4 s01, float4 s23) {
    float4 res;
    {
        float dx = px - s01.x, dy = py - s01.y;
        res.x = j0_scaled(KW * __fsqrt_rn(fmaf(dx, dx, dy * dy)));
    }
    {
        float dx = px - s01.z, dy = py - s01.w;
        res.y = j0_scaled(KW * __fsqrt_rn(fmaf(dx, dx, dy * dy)));
    }
    {
        float dx = px - s23.x, dy = py - s23.y;
        res.z = j0_scaled(KW * __fsqrt_rn(fmaf(dx, dx, dy * dy)));
    }
    {
        float dx = px - s23.z, dy = py - s23.w;
        res.w = j0_scaled(KW * __fsqrt_rn(fmaf(dx, dx, dy * dy)));
    }
    return res;
}

#define ROWS_PER_CTA 8

__global__ void __launch_bounds__(256, 2) pikf_kernel(
    const float* __restrict__ p,
    const float* __restrict__ src,
    float* __restrict__ out,
    int N, int Mq)   // Mq = M/4
{
    int j4 = blockIdx.x * blockDim.x + threadIdx.x;
    if (j4 >= Mq) return;
    int i0 = blockIdx.y * ROWS_PER_CTA;

    // 4 source nodes: interleaved (x,y) pairs -> two float4 loads, coalesced
    const float4* src4 = reinterpret_cast<const float4*>(src);
    float4 s01 = src4[2 * j4 + 0];   // (x0,y0,x1,y1)
    float4 s23 = src4[2 * j4 + 1];   // (x2,y2,x3,y3)

    const float2* p2 = reinterpret_cast<const float2*>(p);
    float4* orow = reinterpret_cast<float4*>(out) + (size_t)i0 * Mq + j4;

    if (i0 + ROWS_PER_CTA <= N) {
        // full tile: no per-row guard
        #pragma unroll
        for (int iv = 0; iv < ROWS_PER_CTA; ++iv) {
            float2 pi = __ldg(&p2[i0 + iv]);
            *orow = row_vals(pi.x, pi.y, s01, s23);
            orow += Mq;
        }
    } else {
        int irows = N - i0;
        for (int iv = 0; iv < irows; ++iv) {
            float2 pi = __ldg(&p2[i0 + iv]);
            *orow = row_vals(pi.x, pi.y, s01, s23);
            orow += Mq;
        }
    }
}

extern "C" void kernel_launch(void* const* d_in, const int* in_sizes, int n_in,
                              void* d_out, int out_size) {
    const float* p   = (const float*)d_in[0];   // (N, 2)
    const float* src = (const float*)d_in[1];   // (M, 2)
    int N = in_sizes[0] / 2;
    int M = in_sizes[1] / 2;
    int Mq = M / 4;   // M = 5000 -> 1250 float4 groups per row

    dim3 block(256);
    dim3 grid((Mq + block.x - 1) / block.x, (N + ROWS_PER_CTA - 1) / ROWS_PER_CTA);
    pikf_kernel<<<grid, block>>>(p, src, (float*)d_out, N, Mq);
}

// round 6
// speedup vs baseline: 1.1801x; 1.1801x over previous
#include <cuda_runtime.h>
#include <cuda_bf16.h>

// out[i, j] = J0(1000 * |p_i - s_j|) / (2*pi),  N=10000, M=5000 (fp32)
//
// Packed-f32x2 kernel: all FADD/FMUL/FFMA arithmetic runs 2 elements per
// instruction (SASS FFMA2 etc., PTX-only forms). MUFU ops stay scalar:
// 4 MUFU/elem (RSQ, SQRT, SIN, COS) -> MUFU-bound.
//
// Precision:
//  - r via rsqrt.approx + one FMA residual correction
//    r' = r0 + (r2 - r0*r0) * (-0.5*y0): quadratic convergence from ~2ulp
//    seed lands within ~1-2 ulp of correctly-rounded sqrt, so the phase
//    xx = 1000*r - pi/4 tracks the reference to ~ulp level.
//  - Cody-Waite reduction mod 2pi (C1=6.28125: 8 mantissa bits, n*C1 exact
//    for n<=~1600), __sincosf on reduced arg in [-pi,pi].
//  - y0 ~ 1/r feeds z=8/ax and amp=K2*sqrt(y0) (low-sensitivity terms).

typedef unsigned long long u64;

#define PK(dst, lo, hi)  asm("mov.b64 %0, {%1, %2};" : "=l"(dst) : "f"(lo), "f"(hi))
#define UPK(lo, hi, src) asm("mov.b64 {%0, %1}, %2;" : "=f"(lo), "=f"(hi) : "l"(src))
#define FMA2(d,a,b,c) asm("fma.rn.f32x2 %0, %1, %2, %3;" : "=l"(d) : "l"(a), "l"(b), "l"(c))
#define MUL2(d,a,b)   asm("mul.rn.f32x2 %0, %1, %2;"     : "=l"(d) : "l"(a), "l"(b))
#define ADD2(d,a,b)   asm("add.rn.f32x2 %0, %1, %2;"     : "=l"(d) : "l"(a), "l"(b))

__device__ __forceinline__ float rsqrt_approx(float x) {
    float r; asm("rsqrt.approx.f32 %0, %1;" : "=f"(r) : "f"(x)); return r;
}
__device__ __forceinline__ float sqrt_approx(float x) {
    float r; asm("sqrt.approx.f32 %0, %1;" : "=f"(r) : "f"(x)); return r;
}
__device__ __forceinline__ u64 pk2(float v) { u64 d; PK(d, v, v); return d; }

#define INV_2PI   0.15915494309189535f
#define MAGICF    12582912.0f            // 1.5 * 2^23
// sqrt(0.636619772)/(2pi)
#define SAMPC     0.1269872758f
// SAMPC * sqrt(1e-3)  (amp = K2 * sqrt(1/r))
#define K2AMP     0.0040156862f

// Rare scalar fallback (r2 < ~6.45e-5, i.e. ax near/below 8). Handles both
// reference branches exactly.
__device__ __noinline__ float j0_scalar_ref(float r2) {
    float ax = 1000.0f * __fsqrt_rn(r2);
    if (ax < 8.0f) {
        float y = ax * ax;
        float num = 57568490574.0f + y * (-13362590354.0f + y * (651619640.7f
                  + y * (-11214424.18f + y * (77392.33017f + y * (-184.9052456f)))));
        float den = 57568490411.0f + y * (1029532985.0f + y * (9494680.718f
                  + y * (59272.64853f + y * (267.8532712f + y))));
        return __fdividef(num, den) * INV_2PI;
    }
    float rsq = rsqrt_approx(ax);
    float inv_ax = rsq * rsq;
    float z = 8.0f * inv_ax, y2 = z * z;
    float xx = ax - 0.785398164f;
    float t = fmaf(xx, INV_2PI, MAGICF);
    float n = t - MAGICF;
    float red = fmaf(n, -6.28125f, xx);
    red = fmaf(n, -0.0019353071795864769f, red);
    float s, c; __sincosf(red, &s, &c);
    float p0 = 1.0f + y2 * (-0.1098628627e-2f + y2 * (0.2734510407e-4f
             + y2 * (-0.2073370639e-5f + y2 * 0.2093887211e-6f)));
    float q0 = -0.1562499995e-1f + y2 * (0.1430488765e-3f + y2 * (-0.6911147651e-5f
             + y2 * (0.7621095161e-6f + y2 * (-0.934935152e-7f))));
    float amp = SAMPC * rsq;
    return amp * (c * p0 - z * (s * q0));
}

#define ROWS_PER_CTA 8

__global__ void __launch_bounds__(256, 2) pikf_kernel(
    const float* __restrict__ p,
    const float* __restrict__ src,
    float* __restrict__ out,
    int N, int Mq)   // Mq = M/4
{
    int j4 = blockIdx.x * blockDim.x + threadIdx.x;
    if (j4 >= Mq) return;
    int i0 = blockIdx.y * ROWS_PER_CTA;

    // packed constants (warp-uniform; candidates for UR promotion)
    const u64 k_nhalf = pk2(-0.5f);
    const u64 k_1000  = pk2(1000.0f);
    const u64 k_n8em3 = pk2(-0.008f);          // -8/1000
    const u64 k_amp   = pk2(K2AMP);
    const u64 k_npio4 = pk2(-0.785398164f);
    const u64 k_i2pi  = pk2(INV_2PI);
    const u64 k_magic = pk2(MAGICF);
    const u64 k_nmagic= pk2(-MAGICF);
    const u64 k_nC1   = pk2(-6.28125f);
    const u64 k_nC2   = pk2(-0.0019353071795864769f);
    const u64 k_nOne  = pk2(-1.0f);
    const u64 k_p4 = pk2(0.2093887211e-6f), k_p3 = pk2(-0.2073370639e-5f);
    const u64 k_p2 = pk2(0.2734510407e-4f), k_p1 = pk2(-0.1098628627e-2f);
    const u64 k_p0 = pk2(1.0f);
    const u64 k_q4 = pk2(-0.934935152e-7f), k_q3 = pk2(0.7621095161e-6f);
    const u64 k_q2 = pk2(-0.6911147651e-5f), k_q1 = pk2(0.1430488765e-3f);
    const u64 k_q0 = pk2(-0.1562499995e-1f);

    // 4 source nodes -> two packed pairs (lanes: lo=even col, hi=odd col)
    const float4* src4 = reinterpret_cast<const float4*>(src);
    float4 s01 = src4[2 * j4 + 0];   // (x0,y0,x1,y1)
    float4 s23 = src4[2 * j4 + 1];   // (x2,y2,x3,y3)
    u64 nsxA, nsyA, nsxB, nsyB;
    PK(nsxA, -s01.x, -s01.z); PK(nsyA, -s01.y, -s01.w);
    PK(nsxB, -s23.x, -s23.z); PK(nsyB, -s23.y, -s23.w);

    auto eval2 = [&](u64 pxp, u64 pyp, u64 nsx, u64 nsy) -> u64 {
        u64 dx, dy, t, r2;
        ADD2(dx, pxp, nsx);
        ADD2(dy, pyp, nsy);
        MUL2(t, dy, dy);
        FMA2(r2, dx, dx, t);
        float r2a, r2b; UPK(r2a, r2b, r2);
        if (__builtin_expect(fminf(r2a, r2b) < 6.45e-5f, 0)) {
            float ra = j0_scalar_ref(r2a);
            float rb = j0_scalar_ref(r2b);
            u64 resf; PK(resf, ra, rb); return resf;
        }
        // y0 ~ 1/r (rsqrt.approx, ~2ulp). r = r2*y0 then one FMA residual
        // correction -> ~1-2 ulp of true sqrt (quadratic convergence).
        float y0a = rsqrt_approx(r2a), y0b = rsqrt_approx(r2b);
        u64 y0; PK(y0, y0a, y0b);
        u64 rr0; MUL2(rr0, r2, y0);
        u64 nr2; MUL2(nr2, r2, k_nOne);
        u64 d;   FMA2(d, rr0, rr0, nr2);       // r0^2 - r2 (fused, small)
        u64 hy;  MUL2(hy, y0, k_nhalf);        // -0.5/r
        u64 rr;  FMA2(rr, d, hy, rr0);         // corrected r
        u64 ax;  MUL2(ax, rr, k_1000);
        u64 nz;  MUL2(nz, y0, k_n8em3);        // -z = -8/ax
        u64 y2;  MUL2(y2, nz, nz);             // z^2
        // amp = K2 * sqrt(1/r)
        float sqa = sqrt_approx(y0a), sqb = sqrt_approx(y0b);
        u64 sqy; PK(sqy, sqa, sqb);
        u64 amp; MUL2(amp, sqy, k_amp);
        // phase: Cody-Waite mod 2pi, packed
        u64 xx;  ADD2(xx, ax, k_npio4);
        u64 tt;  FMA2(tt, xx, k_i2pi, k_magic);
        u64 nn;  ADD2(nn, tt, k_nmagic);
        u64 red; FMA2(red, nn, k_nC1, xx);
        FMA2(red, nn, k_nC2, red);
        float reda, redb; UPK(reda, redb, red);
        float sa, ca, sb, cb;
        __sincosf(reda, &sa, &ca);
        __sincosf(redb, &sb, &cb);
        u64 sp, cp; PK(sp, sa, sb); PK(cp, ca, cb);
        // polynomials, packed Horner
        u64 P; FMA2(P, y2, k_p4, k_p3); FMA2(P, y2, P, k_p2);
               FMA2(P, y2, P, k_p1);    FMA2(P, y2, P, k_p0);
        u64 Q; FMA2(Q, y2, k_q4, k_q3); FMA2(Q, y2, Q, k_q2);
               FMA2(Q, y2, Q, k_q1);    FMA2(Q, y2, Q, k_q0);
        // res = amp * (c*P + nz*(s*Q))
        u64 sq;  MUL2(sq, sp, Q);
        u64 cP;  MUL2(cP, cp, P);
        u64 comb; FMA2(comb, nz, sq, cP);
        u64 res; MUL2(res, amp, comb);
        return res;
    };

    const float2* p2 = reinterpret_cast<const float2*>(p);
    ulonglong2* orow = reinterpret_cast<ulonglong2*>(out) + (size_t)i0 * Mq + j4;

    if (i0 + ROWS_PER_CTA <= N) {
        #pragma unroll 2
        for (int iv = 0; iv < ROWS_PER_CTA; ++iv) {
            float2 pi = __ldg(&p2[i0 + iv]);
            u64 pxp, pyp; PK(pxp, pi.x, pi.x); PK(pyp, pi.y, pi.y);
            ulonglong2 o;
            o.x = eval2(pxp, pyp, nsxA, nsyA);
            o.y = eval2(pxp, pyp, nsxB, nsyB);
            *orow = o;
            orow += Mq;
        }
    } else {
        int irows = N - i0;
        for (int iv = 0; iv < irows; ++iv) {
            float2 pi = __ldg(&p2[i0 + iv]);
            u64 pxp, pyp; PK(pxp, pi.x, pi.x); PK(pyp, pi.y, pi.y);
            ulonglong2 o;
            o.x = eval2(pxp, pyp, nsxA, nsyA);
            o.y = eval2(pxp, pyp, nsxB, nsyB);
            *orow = o;
            orow += Mq;
        }
    }
}

extern "C" void kernel_launch(void* const* d_in, const int* in_sizes, int n_in,
                              void* d_out, int out_size) {
    const float* p   = (const float*)d_in[0];   // (N, 2)
    const float* src = (const float*)d_in[1];   // (M, 2)
    int N = in_sizes[0] / 2;
    int M = in_sizes[1] / 2;
    int Mq = M / 4;   // M = 5000 -> 1250 float4 groups per row

    dim3 block(256);
    dim3 grid((Mq + block.x - 1) / block.x, (N + ROWS_PER_CTA - 1) / ROWS_PER_CTA);
    pikf_kernel<<<grid, block>>>(p, src, (float*)d_out, N, Mq);
}